// round 13
// baseline (speedup 1.0000x reference)
#include <cuda_runtime.h>
#include <cuda_fp16.h>

#define NSEQ 2048
typedef unsigned uint_t;

// ---------------- device scratch (allocation-free) ----------------
__device__ __align__(16) __half g_qh[2][(size_t)64*NSEQ*64];
__device__ __align__(16) __half g_kh[2][(size_t)64*NSEQ*64];
__device__ __align__(16) __half g_vt[(size_t)64*64*NSEQ];      // transposed V (hi only)
__device__ __align__(16) __half g_w[3][2][1024*1024];          // q,k,v weights
__device__ __align__(16) __half g_wo[1024*1024];               // hi only
__device__ __align__(16) __half g_ao[(size_t)8192*1024];       // fp16 attn out

// ---------------- helpers ----------------
__device__ __forceinline__ uint_t pk(float x, float y){
    __half2 t = __floats2half2_rn(x, y);
    return *(uint_t*)&t;
}
__device__ __forceinline__ void sp2(float x, float y, uint_t& h, uint_t& l){
    float hx = __half2float(__float2half_rn(x));
    float hy = __half2float(__float2half_rn(y));
    h = pk(hx, hy);
    l = pk(x - hx, y - hy);
}
__device__ __forceinline__ float ex2(float x){
    float y;
    asm("ex2.approx.ftz.f32 %0, %1;" : "=f"(y) : "f"(x));
    return y;
}
__device__ __forceinline__ void mma4(float (&d)[4], const uint_t (&a)[4],
                                     uint_t b0, uint_t b1){
    asm volatile(
      "mma.sync.aligned.m16n8k16.row.col.f32.f16.f16.f32 "
      "{%0,%1,%2,%3}, {%4,%5,%6,%7}, {%8,%9}, {%0,%1,%2,%3};\n"
      : "+f"(d[0]), "+f"(d[1]), "+f"(d[2]), "+f"(d[3])
      : "r"(a[0]), "r"(a[1]), "r"(a[2]), "r"(a[3]), "r"(b0), "r"(b1));
}
__device__ __forceinline__ uint_t saddr(const void* p){
    return (uint_t)__cvta_generic_to_shared(p);
}
#define CPA16(dst, src) \
    asm volatile("cp.async.cg.shared.global [%0], [%1], 16;" \
                 :: "r"(dst), "l"(src) : "memory")

// ---------------- weight prep (transpose + 2-level fp16 split) -----------
__global__ __launch_bounds__(256) void prep_w(
    const float* __restrict__ wq, const float* __restrict__ wk,
    const float* __restrict__ wv)
{
    __shared__ float T[32][33];
    const int z = blockIdx.z, sel = z >> 4, h = z & 15;
    const float* W = (sel==0 ? wq : (sel==1 ? wk : wv)) + (size_t)h * 65536;
    __half* O0 = g_w[sel][0] + (size_t)h*64*1024;
    __half* O1 = g_w[sel][1] + (size_t)h*64*1024;
    const int c0 = blockIdx.x*32, d0 = blockIdx.y*32;
    const int tx = threadIdx.x, ty = threadIdx.y;
    #pragma unroll
    for (int i = 0; i < 4; i++)
        T[ty+i*8][tx] = W[(size_t)(d0+ty+i*8)*64 + c0+tx];
    __syncthreads();
    #pragma unroll
    for (int i = 0; i < 4; i++) {
        float v = T[tx][ty+i*8];
        float hv = __half2float(__float2half_rn(v));
        size_t idx = (size_t)(c0+ty+i*8)*1024 + d0+tx;
        O0[idx] = __float2half_rn(hv);
        O1[idx] = __float2half_rn(v - hv);
    }
}
__global__ __launch_bounds__(256) void prep_wo(const float* __restrict__ W)
{
    __shared__ float T[32][33];
    const int n0 = blockIdx.x*32, k0 = blockIdx.y*32;
    const int tx = threadIdx.x, ty = threadIdx.y;
    #pragma unroll
    for (int i = 0; i < 4; i++)
        T[ty+i*8][tx] = W[(size_t)(k0+ty+i*8)*1024 + n0+tx];
    __syncthreads();
    #pragma unroll
    for (int i = 0; i < 4; i++) {
        float v = T[tx][ty+i*8];
        size_t idx = (size_t)(n0+ty+i*8)*1024 + k0+tx;
        g_wo[idx] = __float2half_rn(v);
    }
}

// ---------------- fp16 GEMM tile, fp32 A (128x128, k-step 16) ------------
template<int NP>
__device__ __forceinline__ void gemm_tile2(
    const float* __restrict__ A,
    const __half* __restrict__ B0, const __half* __restrict__ B1,
    int row0, int col0, __half* SM, float (&acc)[4][4][4])
{
    __half* SAl = SM + 3072;
    __half* SB  = SM + (NP == 3 ? 6144 : 3072);

    const int tid = threadIdx.x, w = tid>>5, lane = tid&31;
    const int wm = w>>2, wn = w&3, g = lane>>2, tg = lane&3;
    const int srow = tid>>1, skb = (tid&1)*8;
    const float* Ap = A + (size_t)(row0+srow)*1024 + skb;
    const size_t boff = (size_t)(col0+srow)*1024 + skb;
    const int soff = srow*24 + skb;
    const int kc = tg*2;

    #pragma unroll
    for (int a = 0; a < 4; a++)
        #pragma unroll
        for (int b = 0; b < 4; b++)
            #pragma unroll
            for (int c = 0; c < 4; c++) acc[a][b][c] = 0.f;

    float4 a0 = *(const float4*)Ap, a1 = *(const float4*)(Ap+4);
    uint4 bv0 = *(const uint4*)(B0+boff);
    uint4 bv1;
    if (NP == 3) bv1 = *(const uint4*)(B1+boff);

    #pragma unroll 1
    for (int k0 = 0; k0 < 1024; k0 += 16) {
        if (NP == 3) {
            uint_t h[4], l[4];
            sp2(a0.x,a0.y,h[0],l[0]); sp2(a0.z,a0.w,h[1],l[1]);
            sp2(a1.x,a1.y,h[2],l[2]); sp2(a1.z,a1.w,h[3],l[3]);
            *(uint4*)&SM[soff]  = make_uint4(h[0],h[1],h[2],h[3]);
            *(uint4*)&SAl[soff] = make_uint4(l[0],l[1],l[2],l[3]);
        } else {
            *(uint4*)&SM[soff] = make_uint4(pk(a0.x,a0.y), pk(a0.z,a0.w),
                                            pk(a1.x,a1.y), pk(a1.z,a1.w));
        }
        *(uint4*)&SB[soff] = bv0;
        if (NP == 3) *(uint4*)&SB[3072+soff] = bv1;
        __syncthreads();
        const bool more = (k0 + 16) < 1024;
        if (more) {
            a0 = *(const float4*)(Ap+k0+16); a1 = *(const float4*)(Ap+k0+20);
            bv0 = *(const uint4*)(B0+boff+k0+16);
            if (NP == 3) bv1 = *(const uint4*)(B1+boff+k0+16);
        }
        uint_t bf[2][4][2];
        #pragma unroll
        for (int nf = 0; nf < 4; nf++) {
            int nro = (wn*32+nf*8+g)*24 + kc;
            bf[0][nf][0] = *(const uint_t*)&SB[nro];
            bf[0][nf][1] = *(const uint_t*)&SB[nro+8];
            if (NP == 3) {
                bf[1][nf][0] = *(const uint_t*)&SB[3072+nro];
                bf[1][nf][1] = *(const uint_t*)&SB[3072+nro+8];
            }
        }
        #pragma unroll
        for (int mf = 0; mf < 4; mf++) {
            int mro = (wm*64+mf*16+g)*24 + kc;
            uint_t af0[4], af1[4];
            af0[0] = *(const uint_t*)&SM[mro];
            af0[1] = *(const uint_t*)&SM[mro+192];
            af0[2] = *(const uint_t*)&SM[mro+8];
            af0[3] = *(const uint_t*)&SM[mro+200];
            if (NP == 3) {
                af1[0] = *(const uint_t*)&SAl[mro];
                af1[1] = *(const uint_t*)&SAl[mro+192];
                af1[2] = *(const uint_t*)&SAl[mro+8];
                af1[3] = *(const uint_t*)&SAl[mro+200];
            }
            #pragma unroll
            for (int nf = 0; nf < 4; nf++)
                mma4(acc[mf][nf], af0, bf[0][nf][0], bf[0][nf][1]);
            if (NP == 3) {
                #pragma unroll
                for (int nf = 0; nf < 4; nf++)
                    mma4(acc[mf][nf], af0, bf[1][nf][0], bf[1][nf][1]);
                #pragma unroll
                for (int nf = 0; nf < 4; nf++)
                    mma4(acc[mf][nf], af1, bf[0][nf][0], bf[0][nf][1]);
            }
        }
        __syncthreads();
    }
}

// ---------------- fp16 GEMM tile, fp16 A, 1 pass (out_gemm) --------------
__device__ __forceinline__ void gemm_tile_h1(
    const __half* __restrict__ A, const __half* __restrict__ B0,
    int row0, int col0, __half* SM, float (&acc)[4][4][4])
{
    __half* SB = SM + 3072;

    const int tid = threadIdx.x, w = tid>>5, lane = tid&31;
    const int wm = w>>2, wn = w&3, g = lane>>2, tg = lane&3;
    const int srow = tid>>1, skb = (tid&1)*8;
    const __half* Ap = A + (size_t)(row0+srow)*1024 + skb;
    const size_t boff = (size_t)(col0+srow)*1024 + skb;
    const int soff = srow*24 + skb;
    const int kc = tg*2;

    #pragma unroll
    for (int a = 0; a < 4; a++)
        #pragma unroll
        for (int b = 0; b < 4; b++)
            #pragma unroll
            for (int c = 0; c < 4; c++) acc[a][b][c] = 0.f;

    uint4 av = *(const uint4*)Ap;
    uint4 bv0 = *(const uint4*)(B0+boff);

    #pragma unroll 1
    for (int k0 = 0; k0 < 1024; k0 += 16) {
        *(uint4*)&SM[soff] = av;
        *(uint4*)&SB[soff] = bv0;
        __syncthreads();
        const bool more = (k0 + 16) < 1024;
        if (more) {
            av  = *(const uint4*)(Ap+k0+16);
            bv0 = *(const uint4*)(B0+boff+k0+16);
        }
        uint_t bf[4][2];
        #pragma unroll
        for (int nf = 0; nf < 4; nf++) {
            int nro = (wn*32+nf*8+g)*24 + kc;
            bf[nf][0] = *(const uint_t*)&SB[nro];
            bf[nf][1] = *(const uint_t*)&SB[nro+8];
        }
        #pragma unroll
        for (int mf = 0; mf < 4; mf++) {
            int mro = (wm*64+mf*16+g)*24 + kc;
            uint_t af0[4];
            af0[0] = *(const uint_t*)&SM[mro];
            af0[1] = *(const uint_t*)&SM[mro+192];
            af0[2] = *(const uint_t*)&SM[mro+8];
            af0[3] = *(const uint_t*)&SM[mro+200];
            #pragma unroll
            for (int nf = 0; nf < 4; nf++)
                mma4(acc[mf][nf], af0, bf[nf][0], bf[nf][1]);
        }
        __syncthreads();
    }
}

// ---------------- merged projection kernel (q,k: 3-pass; v: 1-pass) ------
__global__ __launch_bounds__(256) void proj(
    const float* __restrict__ q, const float* __restrict__ k,
    const float* __restrict__ v)
{
    __shared__ __half SM[12288];
    const int z = blockIdx.z;
    float acc[4][4][4];
    const int row0 = blockIdx.x*128, col0 = blockIdx.y*128;
    const int tid = threadIdx.x, w = tid>>5, lane = tid&31;
    const int wm = w>>2, wn = w&3, g = lane>>2, tg = lane&3;

    if (z < 2) {
        gemm_tile2<3>(z ? k : q, g_w[z][0], g_w[z][1], row0, col0, SM, acc);
        __half* O0 = z ? g_kh[0] : g_qh[0];
        __half* O1 = z ? g_kh[1] : g_qh[1];
        #pragma unroll
        for (int mf = 0; mf < 4; mf++) {
            int r = row0 + wm*64 + mf*16 + g;
            int b = r >> 11, n = r & (NSEQ-1);
            #pragma unroll
            for (int nf = 0; nf < 4; nf++) {
                int c = col0 + wn*32 + nf*8 + tg*2;
                size_t idx = (((size_t)(b*16 + (c>>6)))*NSEQ + n)*64 + (c&63);
                uint_t h, l;
                sp2(acc[mf][nf][0], acc[mf][nf][1], h, l);
                *(uint_t*)&O0[idx] = h; *(uint_t*)&O1[idx] = l;
                sp2(acc[mf][nf][2], acc[mf][nf][3], h, l);
                *(uint_t*)&O0[idx+512] = h; *(uint_t*)&O1[idx+512] = l;
            }
        }
    } else {
        gemm_tile2<1>(v, g_w[2][0], g_w[2][0], row0, col0, SM, acc);
        #pragma unroll
        for (int mf = 0; mf < 4; mf++) {
            int r = row0 + wm*64 + mf*16 + g;
            int b = r >> 11, n = r & (NSEQ-1);
            #pragma unroll
            for (int nf = 0; nf < 4; nf++) {
                int c = col0 + wn*32 + nf*8 + tg*2;
                int hh = c >> 6, d = c & 63;
                size_t bi = ((size_t)(b*16 + hh)*64 + d)*NSEQ;
                g_vt[bi + n]            = __float2half_rn(acc[mf][nf][0]);
                g_vt[bi + NSEQ + n]     = __float2half_rn(acc[mf][nf][1]);
                g_vt[bi + n + 8]        = __float2half_rn(acc[mf][nf][2]);
                g_vt[bi + NSEQ + n + 8] = __float2half_rn(acc[mf][nf][3]);
            }
        }
    }
}

// ---------------- flash attention: cp.async double-buffered K/V ----------
// Per buffer (13824 halves): Kh 0, Kl 4608, Vh 9216. Two buffers.
__global__ void __launch_bounds__(256, 2) flash_attn()
{
    extern __shared__ __half sm[];
    const float C = 0.125f * 1.4426950408889634f;

    const int tid = threadIdx.x, w = tid>>5, lane = tid&31;
    const int g = lane>>2, tg = lane&3;
    const int qb = (int)gridDim.x - 1 - (int)blockIdx.x;   // heavy CTAs first
    const int bh = blockIdx.y;
    const int q0 = qb*128;
    const int row0 = q0 + w*16 + g;
    const size_t base = (size_t)bh*NSEQ*64;

    uint_t qf[2][4][4];
    {
        __half* qs = sm + w*1152;
        #pragma unroll
        for (int lv = 0; lv < 2; lv++) {
            const __half* Qs = g_qh[lv];
            #pragma unroll
            for (int it = 0; it < 4; it++) {
                int idx = it*32 + lane;
                int r = idx >> 3, c8 = (idx & 7)*8;
                *(uint4*)&qs[r*72 + c8] =
                    *(const uint4*)&Qs[base + (size_t)(q0+w*16+r)*64 + c8];
            }
            __syncwarp();
            #pragma unroll
            for (int s = 0; s < 4; s++) {
                int kc = s*16 + tg*2;
                qf[lv][s][0] = *(const uint_t*)&qs[g*72+kc];
                qf[lv][s][1] = *(const uint_t*)&qs[(g+8)*72+kc];
                qf[lv][s][2] = *(const uint_t*)&qs[g*72+kc+8];
                qf[lv][s][3] = *(const uint_t*)&qs[(g+8)*72+kc+8];
            }
            __syncwarp();
        }
    }
    __syncthreads();

    const int key = tid >> 2, off = (tid & 3)*16;
    const int srow = key*72 + off;
    const uint_t sb0 = saddr(sm);

    // prologue: async-load tile 0 into buffer 0
    {
        size_t si = base + (size_t)key*64 + off;
        size_t vi = ((size_t)bh*64 + key)*NSEQ + off;
        uint_t d = sb0 + (uint_t)srow*2;
        CPA16(d,            &g_kh[0][si]);
        CPA16(d + 16,       &g_kh[0][si+8]);
        CPA16(d + 9216,     &g_kh[1][si]);       // +4608 halves
        CPA16(d + 9232,     &g_kh[1][si+8]);
        CPA16(d + 18432,    &g_vt[vi]);          // +9216 halves
        CPA16(d + 18448,    &g_vt[vi+8]);
        asm volatile("cp.async.commit_group;" ::: "memory");
    }

    float O[8][4];
    #pragma unroll
    for (int nf = 0; nf < 8; nf++)
        #pragma unroll
        for (int e = 0; e < 4; e++) O[nf][e] = 0.f;
    float m0 = -1e30f, m1 = -1e30f, l0 = 0.f, l1 = 0.f;

    const int ntiles = 2*qb + 2;
    #pragma unroll 1
    for (int kt = 0; kt < ntiles; kt++) {
        asm volatile("cp.async.wait_group 0;" ::: "memory");
        __syncthreads();

        const __half* B = sm + (kt & 1) * 13824;
        const __half* Kh = B;
        const __half* Kl = B + 4608;
        const __half* Vh = B + 9216;

        const bool more = (kt + 1) < ntiles;
        if (more) {   // async-load next tile into other buffer
            size_t si = base + (size_t)((kt+1)*64+key)*64 + off;
            size_t vi = ((size_t)bh*64 + key)*NSEQ + (kt+1)*64 + off;
            uint_t d = sb0 + (uint_t)(((kt+1)&1)*13824 + srow)*2;
            CPA16(d,         &g_kh[0][si]);
            CPA16(d + 16,    &g_kh[0][si+8]);
            CPA16(d + 9216,  &g_kh[1][si]);
            CPA16(d + 9232,  &g_kh[1][si+8]);
            CPA16(d + 18432, &g_vt[vi]);
            CPA16(d + 18448, &g_vt[vi+8]);
            asm volatile("cp.async.commit_group;" ::: "memory");
        }

        if (!((kt == 2*qb+1) && (w < 4))) {
            float S[8][4];
            #pragma unroll
            for (int nf = 0; nf < 8; nf++)
                #pragma unroll
                for (int e = 0; e < 4; e++) S[nf][e] = 0.f;

            // QK^T: passes hh, hl, lh
            #pragma unroll
            for (int s = 0; s < 4; s++) {
                const int kc = s*16 + tg*2;
                #pragma unroll
                for (int hf = 0; hf < 2; hf++) {
                    uint_t kh[4][2], kl[4][2];
                    #pragma unroll
                    for (int q4 = 0; q4 < 4; q4++) {
                        int kr = ((hf*4+q4)*8+g)*72;
                        kh[q4][0] = *(const uint_t*)&Kh[kr+kc];
                        kh[q4][1] = *(const uint_t*)&Kh[kr+kc+8];
                        kl[q4][0] = *(const uint_t*)&Kl[kr+kc];
                        kl[q4][1] = *(const uint_t*)&Kl[kr+kc+8];
                    }
                    float (*Sg)[4] = &S[hf*4];
                    #pragma unroll
                    for (int q4 = 0; q4 < 4; q4++)
                        mma4(Sg[q4], qf[0][s], kh[q4][0], kh[q4][1]);
                    #pragma unroll
                    for (int q4 = 0; q4 < 4; q4++)
                        mma4(Sg[q4], qf[0][s], kl[q4][0], kl[q4][1]);
                    #pragma unroll
                    for (int q4 = 0; q4 < 4; q4++)
                        mma4(Sg[q4], qf[1][s], kh[q4][0], kh[q4][1]);
                }
            }

            const bool maskt = (kt >= 2*qb);
            float rmax0 = -1e30f, rmax1 = -1e30f;
            #pragma unroll
            for (int nf = 0; nf < 8; nf++) {
                int colb = kt*64 + nf*8 + tg*2;
                S[nf][0] *= C; S[nf][1] *= C;
                S[nf][2] *= C; S[nf][3] *= C;
                if (maskt) {
                    if (colb   > row0)   S[nf][0] = -1e30f;
                    if (colb+1 > row0)   S[nf][1] = -1e30f;
                    if (colb   > row0+8) S[nf][2] = -1e30f;
                    if (colb+1 > row0+8) S[nf][3] = -1e30f;
                }
                rmax0 = fmaxf(rmax0, fmaxf(S[nf][0], S[nf][1]));
                rmax1 = fmaxf(rmax1, fmaxf(S[nf][2], S[nf][3]));
            }
            rmax0 = fmaxf(rmax0, __shfl_xor_sync(~0u, rmax0, 1));
            rmax0 = fmaxf(rmax0, __shfl_xor_sync(~0u, rmax0, 2));
            rmax1 = fmaxf(rmax1, __shfl_xor_sync(~0u, rmax1, 1));
            rmax1 = fmaxf(rmax1, __shfl_xor_sync(~0u, rmax1, 2));
            float mn0 = fmaxf(m0, rmax0), mn1 = fmaxf(m1, rmax1);
            float a0 = ex2(m0 - mn0), a1 = ex2(m1 - mn1);
            m0 = mn0; m1 = mn1;
            float rs0 = 0.f, rs1 = 0.f;
            #pragma unroll
            for (int nf = 0; nf < 8; nf++) {
                S[nf][0] = ex2(S[nf][0]-mn0); rs0 += S[nf][0];
                S[nf][1] = ex2(S[nf][1]-mn0); rs0 += S[nf][1];
                S[nf][2] = ex2(S[nf][2]-mn1); rs1 += S[nf][2];
                S[nf][3] = ex2(S[nf][3]-mn1); rs1 += S[nf][3];
            }
            rs0 += __shfl_xor_sync(~0u, rs0, 1); rs0 += __shfl_xor_sync(~0u, rs0, 2);
            rs1 += __shfl_xor_sync(~0u, rs1, 1); rs1 += __shfl_xor_sync(~0u, rs1, 2);
            l0 = l0*a0 + rs0; l1 = l1*a1 + rs1;
            #pragma unroll
            for (int nf = 0; nf < 8; nf++) {
                O[nf][0] *= a0; O[nf][1] *= a0;
                O[nf][2] *= a1; O[nf][3] *= a1;
            }

            // PV: single pass (V hi only)
            #pragma unroll
            for (int s = 0; s < 4; s++) {
                uint_t ph[4];
                ph[0] = pk(S[2*s][0],   S[2*s][1]);
                ph[1] = pk(S[2*s][2],   S[2*s][3]);
                ph[2] = pk(S[2*s+1][0], S[2*s+1][1]);
                ph[3] = pk(S[2*s+1][2], S[2*s+1][3]);
                const int vc = s*16 + tg*2;
                #pragma unroll
                for (int hf = 0; hf < 2; hf++) {
                    uint_t vh[4][2];
                    #pragma unroll
                    for (int q4 = 0; q4 < 4; q4++) {
                        int vr = ((hf*4+q4)*8+g)*72;
                        vh[q4][0] = *(const uint_t*)&Vh[vr+vc];
                        vh[q4][1] = *(const uint_t*)&Vh[vr+vc+8];
                    }
                    float (*Og)[4] = &O[hf*4];
                    #pragma unroll
                    for (int q4 = 0; q4 < 4; q4++)
                        mma4(Og[q4], ph, vh[q4][0], vh[q4][1]);
                }
            }
        }
    }

    const float inv0 = 1.f/l0, inv1 = 1.f/l1;
    const size_t or0 = ((size_t)(bh>>4)*NSEQ + row0)*1024 + (bh&15)*64;
    #pragma unroll
    for (int nf = 0; nf < 8; nf++) {
        int c = nf*8 + tg*2;
        *(uint_t*)&g_ao[or0 + c]        = pk(O[nf][0]*inv0, O[nf][1]*inv0);
        *(uint_t*)&g_ao[or0 + 8192 + c] = pk(O[nf][2]*inv1, O[nf][3]*inv1);
    }
}

// ---------------- output GEMM (1-pass, fp16 A) ----------------
__global__ __launch_bounds__(256) void out_gemm(float* __restrict__ out)
{
    __shared__ __half SM[6144];
    float acc[4][4][4];
    const int row0 = blockIdx.x*128, col0 = blockIdx.y*128;
    gemm_tile_h1(g_ao, g_wo, row0, col0, SM, acc);
    const int tid = threadIdx.x, w = tid>>5, lane = tid&31;
    const int wm = w>>2, wn = w&3, g = lane>>2, tg = lane&3;
    #pragma unroll
    for (int mf = 0; mf < 4; mf++) {
        int r = row0 + wm*64 + mf*16 + g;
        #pragma unroll
        for (int nf = 0; nf < 4; nf++) {
            int c = col0 + wn*32 + nf*8 + tg*2;
            *(float2*)&out[(size_t)r*1024 + c] =
                make_float2(acc[mf][nf][0], acc[mf][nf][1]);
            *(float2*)&out[(size_t)(r+8)*1024 + c] =
                make_float2(acc[mf][nf][2], acc[mf][nf][3]);
        }
    }
}

// ---------------- launch ----------------
extern "C" void kernel_launch(void* const* d_in, const int* in_sizes, int n_in,
                              void* d_out, int out_size)
{
    (void)in_sizes; (void)n_in; (void)out_size;
    const float* q   = (const float*)d_in[0];
    const float* k   = (const float*)d_in[1];
    const float* v   = (const float*)d_in[2];
    const float* w_q = (const float*)d_in[3];
    const float* w_k = (const float*)d_in[4];
    const float* w_v = (const float*)d_in[5];
    const float* w_o = (const float*)d_in[6];
    float* out = (float*)d_out;

    const int flash_smem = 2 * 13824 * 2;   // 55296 B
    cudaFuncSetAttribute(flash_attn,
        cudaFuncAttributeMaxDynamicSharedMemorySize, flash_smem);

    dim3 tb(32, 8);
    prep_w <<<dim3(2, 32, 48), tb>>>(w_q, w_k, w_v);
    prep_wo<<<dim3(32, 32), tb>>>(w_o);

    proj<<<dim3(64, 8, 3), 256>>>(q, k, v);
    flash_attn<<<dim3(16, 64), 256, flash_smem>>>();
    out_gemm<<<dim3(64, 8), 256>>>(out);
}

// round 14
// speedup vs baseline: 1.5440x; 1.5440x over previous
#include <cuda_runtime.h>
#include <cuda_fp16.h>

#define NSEQ 2048
typedef unsigned uint_t;

// ---------------- device scratch (allocation-free) ----------------
__device__ __align__(16) __half g_qh[2][(size_t)64*NSEQ*64];
__device__ __align__(16) __half g_kh[2][(size_t)64*NSEQ*64];
__device__ __align__(16) __half g_vt[(size_t)64*64*NSEQ];      // transposed V (hi only)
__device__ __align__(16) __half g_w[3][2][1024*1024];          // q,k,v weights
__device__ __align__(16) __half g_wo[1024*1024];               // hi only
__device__ __align__(16) __half g_ao[(size_t)8192*1024];       // fp16 attn out

// ---------------- helpers ----------------
__device__ __forceinline__ uint_t pk(float x, float y){
    __half2 t = __floats2half2_rn(x, y);
    return *(uint_t*)&t;
}
__device__ __forceinline__ void sp2(float x, float y, uint_t& h, uint_t& l){
    float hx = __half2float(__float2half_rn(x));
    float hy = __half2float(__float2half_rn(y));
    h = pk(hx, hy);
    l = pk(x - hx, y - hy);
}
__device__ __forceinline__ float ex2(float x){
    float y;
    asm("ex2.approx.ftz.f32 %0, %1;" : "=f"(y) : "f"(x));
    return y;
}
__device__ __forceinline__ void mma4(float (&d)[4], const uint_t (&a)[4],
                                     uint_t b0, uint_t b1){
    asm volatile(
      "mma.sync.aligned.m16n8k16.row.col.f32.f16.f16.f32 "
      "{%0,%1,%2,%3}, {%4,%5,%6,%7}, {%8,%9}, {%0,%1,%2,%3};\n"
      : "+f"(d[0]), "+f"(d[1]), "+f"(d[2]), "+f"(d[3])
      : "r"(a[0]), "r"(a[1]), "r"(a[2]), "r"(a[3]), "r"(b0), "r"(b1));
}

// ---------------- weight prep (transpose + 2-level fp16 split) -----------
__global__ __launch_bounds__(256) void prep_w(
    const float* __restrict__ wq, const float* __restrict__ wk,
    const float* __restrict__ wv)
{
    __shared__ float T[32][33];
    const int z = blockIdx.z, sel = z >> 4, h = z & 15;
    const float* W = (sel==0 ? wq : (sel==1 ? wk : wv)) + (size_t)h * 65536;
    __half* O0 = g_w[sel][0] + (size_t)h*64*1024;
    __half* O1 = g_w[sel][1] + (size_t)h*64*1024;
    const int c0 = blockIdx.x*32, d0 = blockIdx.y*32;
    const int tx = threadIdx.x, ty = threadIdx.y;
    #pragma unroll
    for (int i = 0; i < 4; i++)
        T[ty+i*8][tx] = W[(size_t)(d0+ty+i*8)*64 + c0+tx];
    __syncthreads();
    #pragma unroll
    for (int i = 0; i < 4; i++) {
        float v = T[tx][ty+i*8];
        float hv = __half2float(__float2half_rn(v));
        size_t idx = (size_t)(c0+ty+i*8)*1024 + d0+tx;
        O0[idx] = __float2half_rn(hv);
        O1[idx] = __float2half_rn(v - hv);
    }
}
__global__ __launch_bounds__(256) void prep_wo(const float* __restrict__ W)
{
    __shared__ float T[32][33];
    const int n0 = blockIdx.x*32, k0 = blockIdx.y*32;
    const int tx = threadIdx.x, ty = threadIdx.y;
    #pragma unroll
    for (int i = 0; i < 4; i++)
        T[ty+i*8][tx] = W[(size_t)(k0+ty+i*8)*1024 + n0+tx];
    __syncthreads();
    #pragma unroll
    for (int i = 0; i < 4; i++) {
        float v = T[tx][ty+i*8];
        size_t idx = (size_t)(n0+ty+i*8)*1024 + k0+tx;
        g_wo[idx] = __float2half_rn(v);
    }
}

// ---------------- fp16 GEMM tile, fp32 A (128x128, k-step 16) ------------
// NP=3: A split hi/lo, B hi/lo, passes hh+hl+lh (logit-grade, Q/K).
// NP=1: A plain fp16, B hi only, 1 pass (V projection).
template<int NP>
__device__ __forceinline__ void gemm_tile2(
    const float* __restrict__ A,
    const __half* __restrict__ B0, const __half* __restrict__ B1,
    int row0, int col0, __half* SM, float (&acc)[4][4][4])
{
    __half* SAl = SM + 3072;
    __half* SB  = SM + (NP == 3 ? 6144 : 3072);

    const int tid = threadIdx.x, w = tid>>5, lane = tid&31;
    const int wm = w>>2, wn = w&3, g = lane>>2, tg = lane&3;
    const int srow = tid>>1, skb = (tid&1)*8;
    const float* Ap = A + (size_t)(row0+srow)*1024 + skb;
    const size_t boff = (size_t)(col0+srow)*1024 + skb;
    const int soff = srow*24 + skb;
    const int kc = tg*2;

    #pragma unroll
    for (int a = 0; a < 4; a++)
        #pragma unroll
        for (int b = 0; b < 4; b++)
            #pragma unroll
            for (int c = 0; c < 4; c++) acc[a][b][c] = 0.f;

    float4 a0 = *(const float4*)Ap, a1 = *(const float4*)(Ap+4);
    uint4 bv0 = *(const uint4*)(B0+boff);
    uint4 bv1;
    if (NP == 3) bv1 = *(const uint4*)(B1+boff);

    #pragma unroll 1
    for (int k0 = 0; k0 < 1024; k0 += 16) {
        if (NP == 3) {
            uint_t h[4], l[4];
            sp2(a0.x,a0.y,h[0],l[0]); sp2(a0.z,a0.w,h[1],l[1]);
            sp2(a1.x,a1.y,h[2],l[2]); sp2(a1.z,a1.w,h[3],l[3]);
            *(uint4*)&SM[soff]  = make_uint4(h[0],h[1],h[2],h[3]);
            *(uint4*)&SAl[soff] = make_uint4(l[0],l[1],l[2],l[3]);
        } else {
            *(uint4*)&SM[soff] = make_uint4(pk(a0.x,a0.y), pk(a0.z,a0.w),
                                            pk(a1.x,a1.y), pk(a1.z,a1.w));
        }
        *(uint4*)&SB[soff] = bv0;
        if (NP == 3) *(uint4*)&SB[3072+soff] = bv1;
        __syncthreads();
        const bool more = (k0 + 16) < 1024;
        if (more) {
            a0 = *(const float4*)(Ap+k0+16); a1 = *(const float4*)(Ap+k0+20);
            bv0 = *(const uint4*)(B0+boff+k0+16);
            if (NP == 3) bv1 = *(const uint4*)(B1+boff+k0+16);
        }
        uint_t bf[2][4][2];
        #pragma unroll
        for (int nf = 0; nf < 4; nf++) {
            int nro = (wn*32+nf*8+g)*24 + kc;
            bf[0][nf][0] = *(const uint_t*)&SB[nro];
            bf[0][nf][1] = *(const uint_t*)&SB[nro+8];
            if (NP == 3) {
                bf[1][nf][0] = *(const uint_t*)&SB[3072+nro];
                bf[1][nf][1] = *(const uint_t*)&SB[3072+nro+8];
            }
        }
        #pragma unroll
        for (int mf = 0; mf < 4; mf++) {
            int mro = (wm*64+mf*16+g)*24 + kc;
            uint_t af0[4], af1[4];
            af0[0] = *(const uint_t*)&SM[mro];
            af0[1] = *(const uint_t*)&SM[mro+192];
            af0[2] = *(const uint_t*)&SM[mro+8];
            af0[3] = *(const uint_t*)&SM[mro+200];
            if (NP == 3) {
                af1[0] = *(const uint_t*)&SAl[mro];
                af1[1] = *(const uint_t*)&SAl[mro+192];
                af1[2] = *(const uint_t*)&SAl[mro+8];
                af1[3] = *(const uint_t*)&SAl[mro+200];
            }
            #pragma unroll
            for (int nf = 0; nf < 4; nf++)
                mma4(acc[mf][nf], af0, bf[0][nf][0], bf[0][nf][1]);
            if (NP == 3) {
                #pragma unroll
                for (int nf = 0; nf < 4; nf++)
                    mma4(acc[mf][nf], af0, bf[1][nf][0], bf[1][nf][1]);
                #pragma unroll
                for (int nf = 0; nf < 4; nf++)
                    mma4(acc[mf][nf], af1, bf[0][nf][0], bf[0][nf][1]);
            }
        }
        __syncthreads();
    }
}

// ---------------- fp16 GEMM tile, fp16 A, 1 pass (out_gemm) --------------
__device__ __forceinline__ void gemm_tile_h1(
    const __half* __restrict__ A, const __half* __restrict__ B0,
    int row0, int col0, __half* SM, float (&acc)[4][4][4])
{
    __half* SB = SM + 3072;

    const int tid = threadIdx.x, w = tid>>5, lane = tid&31;
    const int wm = w>>2, wn = w&3, g = lane>>2, tg = lane&3;
    const int srow = tid>>1, skb = (tid&1)*8;
    const __half* Ap = A + (size_t)(row0+srow)*1024 + skb;
    const size_t boff = (size_t)(col0+srow)*1024 + skb;
    const int soff = srow*24 + skb;
    const int kc = tg*2;

    #pragma unroll
    for (int a = 0; a < 4; a++)
        #pragma unroll
        for (int b = 0; b < 4; b++)
            #pragma unroll
            for (int c = 0; c < 4; c++) acc[a][b][c] = 0.f;

    uint4 av = *(const uint4*)Ap;
    uint4 bv0 = *(const uint4*)(B0+boff);

    #pragma unroll 1
    for (int k0 = 0; k0 < 1024; k0 += 16) {
        *(uint4*)&SM[soff] = av;
        *(uint4*)&SB[soff] = bv0;
        __syncthreads();
        const bool more = (k0 + 16) < 1024;
        if (more) {
            av  = *(const uint4*)(Ap+k0+16);
            bv0 = *(const uint4*)(B0+boff+k0+16);
        }
        uint_t bf[4][2];
        #pragma unroll
        for (int nf = 0; nf < 4; nf++) {
            int nro = (wn*32+nf*8+g)*24 + kc;
            bf[nf][0] = *(const uint_t*)&SB[nro];
            bf[nf][1] = *(const uint_t*)&SB[nro+8];
        }
        #pragma unroll
        for (int mf = 0; mf < 4; mf++) {
            int mro = (wm*64+mf*16+g)*24 + kc;
            uint_t af0[4];
            af0[0] = *(const uint_t*)&SM[mro];
            af0[1] = *(const uint_t*)&SM[mro+192];
            af0[2] = *(const uint_t*)&SM[mro+8];
            af0[3] = *(const uint_t*)&SM[mro+200];
            #pragma unroll
            for (int nf = 0; nf < 4; nf++)
                mma4(acc[mf][nf], af0, bf[nf][0], bf[nf][1]);
        }
        __syncthreads();
    }
}

// ---------------- merged projection kernel (q,k: 3-pass; v: 1-pass) ------
__global__ __launch_bounds__(256) void proj(
    const float* __restrict__ q, const float* __restrict__ k,
    const float* __restrict__ v)
{
    __shared__ __half SM[12288];
    const int z = blockIdx.z;
    float acc[4][4][4];
    const int row0 = blockIdx.x*128, col0 = blockIdx.y*128;
    const int tid = threadIdx.x, w = tid>>5, lane = tid&31;
    const int wm = w>>2, wn = w&3, g = lane>>2, tg = lane&3;

    if (z < 2) {
        gemm_tile2<3>(z ? k : q, g_w[z][0], g_w[z][1], row0, col0, SM, acc);
        __half* O0 = z ? g_kh[0] : g_qh[0];
        __half* O1 = z ? g_kh[1] : g_qh[1];
        #pragma unroll
        for (int mf = 0; mf < 4; mf++) {
            int r = row0 + wm*64 + mf*16 + g;
            int b = r >> 11, n = r & (NSEQ-1);
            #pragma unroll
            for (int nf = 0; nf < 4; nf++) {
                int c = col0 + wn*32 + nf*8 + tg*2;
                size_t idx = (((size_t)(b*16 + (c>>6)))*NSEQ + n)*64 + (c&63);
                uint_t h, l;
                sp2(acc[mf][nf][0], acc[mf][nf][1], h, l);
                *(uint_t*)&O0[idx] = h; *(uint_t*)&O1[idx] = l;
                sp2(acc[mf][nf][2], acc[mf][nf][3], h, l);
                *(uint_t*)&O0[idx+512] = h; *(uint_t*)&O1[idx+512] = l;
            }
        }
    } else {
        gemm_tile2<1>(v, g_w[2][0], g_w[2][0], row0, col0, SM, acc);
        #pragma unroll
        for (int mf = 0; mf < 4; mf++) {
            int r = row0 + wm*64 + mf*16 + g;
            int b = r >> 11, n = r & (NSEQ-1);
            #pragma unroll
            for (int nf = 0; nf < 4; nf++) {
                int c = col0 + wn*32 + nf*8 + tg*2;
                int hh = c >> 6, d = c & 63;
                size_t bi = ((size_t)(b*16 + hh)*64 + d)*NSEQ;
                g_vt[bi + n]            = __float2half_rn(acc[mf][nf][0]);
                g_vt[bi + NSEQ + n]     = __float2half_rn(acc[mf][nf][1]);
                g_vt[bi + n + 8]        = __float2half_rn(acc[mf][nf][2]);
                g_vt[bi + NSEQ + n + 8] = __float2half_rn(acc[mf][nf][3]);
            }
        }
    }
}

// ---------------- flash attention (3-pass QK, 1-pass PV, 2 CTA/SM) -------
__global__ void __launch_bounds__(256, 2) flash_attn()
{
    __shared__ __half sm[3*4608];   // Kh 0, Kl 4608, Vh 9216
    __half* Kh = sm;
    __half* Kl = sm + 4608;
    __half* Vh = sm + 9216;

    const float C = 0.125f * 1.4426950408889634f;

    const int tid = threadIdx.x, w = tid>>5, lane = tid&31;
    const int g = lane>>2, tg = lane&3;
    const int qb = (int)gridDim.x - 1 - (int)blockIdx.x;   // heavy CTAs first
    const int bh = blockIdx.y;
    const int q0 = qb*128;
    const int row0 = q0 + w*16 + g;
    const size_t base = (size_t)bh*NSEQ*64;

    uint_t qf[2][4][4];
    {
        __half* qs = sm + w*1152;
        #pragma unroll
        for (int lv = 0; lv < 2; lv++) {
            const __half* Qs = g_qh[lv];
            #pragma unroll
            for (int it = 0; it < 4; it++) {
                int idx = it*32 + lane;
                int r = idx >> 3, c8 = (idx & 7)*8;
                *(uint4*)&qs[r*72 + c8] =
                    *(const uint4*)&Qs[base + (size_t)(q0+w*16+r)*64 + c8];
            }
            __syncwarp();
            #pragma unroll
            for (int s = 0; s < 4; s++) {
                int kc = s*16 + tg*2;
                qf[lv][s][0] = *(const uint_t*)&qs[g*72+kc];
                qf[lv][s][1] = *(const uint_t*)&qs[(g+8)*72+kc];
                qf[lv][s][2] = *(const uint_t*)&qs[g*72+kc+8];
                qf[lv][s][3] = *(const uint_t*)&qs[(g+8)*72+kc+8];
            }
            __syncwarp();
        }
    }
    __syncthreads();

    float O[8][4];
    #pragma unroll
    for (int nf = 0; nf < 8; nf++)
        #pragma unroll
        for (int e = 0; e < 4; e++) O[nf][e] = 0.f;
    float m0 = -1e30f, m1 = -1e30f, l0 = 0.f, l1 = 0.f;

    const int ntiles = 2*qb + 2;
    #pragma unroll 1
    for (int kt = 0; kt < ntiles; kt++) {
        {
            int key = tid >> 2, off = (tid & 3)*16;
            size_t si = base + (size_t)(kt*64+key)*64 + off;
            *(uint4*)&Kh[key*72+off]   = *(const uint4*)&g_kh[0][si];
            *(uint4*)&Kh[key*72+off+8] = *(const uint4*)&g_kh[0][si+8];
            *(uint4*)&Kl[key*72+off]   = *(const uint4*)&g_kh[1][si];
            *(uint4*)&Kl[key*72+off+8] = *(const uint4*)&g_kh[1][si+8];
            size_t vi = ((size_t)bh*64 + key)*NSEQ + kt*64 + off;
            *(uint4*)&Vh[key*72+off]   = *(const uint4*)&g_vt[vi];
            *(uint4*)&Vh[key*72+off+8] = *(const uint4*)&g_vt[vi+8];
        }
        __syncthreads();

        if (!((kt == 2*qb+1) && (w < 4))) {
            float S[8][4];
            #pragma unroll
            for (int nf = 0; nf < 8; nf++)
                #pragma unroll
                for (int e = 0; e < 4; e++) S[nf][e] = 0.f;

            // QK^T: passes hh, hl, lh
            #pragma unroll
            for (int s = 0; s < 4; s++) {
                const int kc = s*16 + tg*2;
                #pragma unroll
                for (int hf = 0; hf < 2; hf++) {
                    uint_t kh[4][2], kl[4][2];
                    #pragma unroll
                    for (int q4 = 0; q4 < 4; q4++) {
                        int kr = ((hf*4+q4)*8+g)*72;
                        kh[q4][0] = *(const uint_t*)&Kh[kr+kc];
                        kh[q4][1] = *(const uint_t*)&Kh[kr+kc+8];
                        kl[q4][0] = *(const uint_t*)&Kl[kr+kc];
                        kl[q4][1] = *(const uint_t*)&Kl[kr+kc+8];
                    }
                    float (*Sg)[4] = &S[hf*4];
                    #pragma unroll
                    for (int q4 = 0; q4 < 4; q4++)
                        mma4(Sg[q4], qf[0][s], kh[q4][0], kh[q4][1]);
                    #pragma unroll
                    for (int q4 = 0; q4 < 4; q4++)
                        mma4(Sg[q4], qf[0][s], kl[q4][0], kl[q4][1]);
                    #pragma unroll
                    for (int q4 = 0; q4 < 4; q4++)
                        mma4(Sg[q4], qf[1][s], kh[q4][0], kh[q4][1]);
                }
            }

            const bool maskt = (kt >= 2*qb);
            float rmax0 = -1e30f, rmax1 = -1e30f;
            #pragma unroll
            for (int nf = 0; nf < 8; nf++) {
                int colb = kt*64 + nf*8 + tg*2;
                S[nf][0] *= C; S[nf][1] *= C;
                S[nf][2] *= C; S[nf][3] *= C;
                if (maskt) {
                    if (colb   > row0)   S[nf][0] = -1e30f;
                    if (colb+1 > row0)   S[nf][1] = -1e30f;
                    if (colb   > row0+8) S[nf][2] = -1e30f;
                    if (colb+1 > row0+8) S[nf][3] = -1e30f;
                }
                rmax0 = fmaxf(rmax0, fmaxf(S[nf][0], S[nf][1]));
                rmax1 = fmaxf(rmax1, fmaxf(S[nf][2], S[nf][3]));
            }
            rmax0 = fmaxf(rmax0, __shfl_xor_sync(~0u, rmax0, 1));
            rmax0 = fmaxf(rmax0, __shfl_xor_sync(~0u, rmax0, 2));
            rmax1 = fmaxf(rmax1, __shfl_xor_sync(~0u, rmax1, 1));
            rmax1 = fmaxf(rmax1, __shfl_xor_sync(~0u, rmax1, 2));
            float mn0 = fmaxf(m0, rmax0), mn1 = fmaxf(m1, rmax1);
            float a0 = ex2(m0 - mn0), a1 = ex2(m1 - mn1);
            m0 = mn0; m1 = mn1;
            float rs0 = 0.f, rs1 = 0.f;
            #pragma unroll
            for (int nf = 0; nf < 8; nf++) {
                S[nf][0] = ex2(S[nf][0]-mn0); rs0 += S[nf][0];
                S[nf][1] = ex2(S[nf][1]-mn0); rs0 += S[nf][1];
                S[nf][2] = ex2(S[nf][2]-mn1); rs1 += S[nf][2];
                S[nf][3] = ex2(S[nf][3]-mn1); rs1 += S[nf][3];
            }
            rs0 += __shfl_xor_sync(~0u, rs0, 1); rs0 += __shfl_xor_sync(~0u, rs0, 2);
            rs1 += __shfl_xor_sync(~0u, rs1, 1); rs1 += __shfl_xor_sync(~0u, rs1, 2);
            l0 = l0*a0 + rs0; l1 = l1*a1 + rs1;
            #pragma unroll
            for (int nf = 0; nf < 8; nf++) {
                O[nf][0] *= a0; O[nf][1] *= a0;
                O[nf][2] *= a1; O[nf][3] *= a1;
            }

            // PV: single pass (V hi only)
            #pragma unroll
            for (int s = 0; s < 4; s++) {
                uint_t ph[4];
                ph[0] = pk(S[2*s][0],   S[2*s][1]);
                ph[1] = pk(S[2*s][2],   S[2*s][3]);
                ph[2] = pk(S[2*s+1][0], S[2*s+1][1]);
                ph[3] = pk(S[2*s+1][2], S[2*s+1][3]);
                const int vc = s*16 + tg*2;
                #pragma unroll
                for (int hf = 0; hf < 2; hf++) {
                    uint_t vh[4][2];
                    #pragma unroll
                    for (int q4 = 0; q4 < 4; q4++) {
                        int vr = ((hf*4+q4)*8+g)*72;
                        vh[q4][0] = *(const uint_t*)&Vh[vr+vc];
                        vh[q4][1] = *(const uint_t*)&Vh[vr+vc+8];
                    }
                    float (*Og)[4] = &O[hf*4];
                    #pragma unroll
                    for (int q4 = 0; q4 < 4; q4++)
                        mma4(Og[q4], ph, vh[q4][0], vh[q4][1]);
                }
            }
        }
        __syncthreads();
    }

    const float inv0 = 1.f/l0, inv1 = 1.f/l1;
    const size_t or0 = ((size_t)(bh>>4)*NSEQ + row0)*1024 + (bh&15)*64;
    #pragma unroll
    for (int nf = 0; nf < 8; nf++) {
        int c = nf*8 + tg*2;
        *(uint_t*)&g_ao[or0 + c]        = pk(O[nf][0]*inv0, O[nf][1]*inv0);
        *(uint_t*)&g_ao[or0 + 8192 + c] = pk(O[nf][2]*inv1, O[nf][3]*inv1);
    }
}

// ---------------- output GEMM (1-pass, fp16 A) ----------------
__global__ __launch_bounds__(256) void out_gemm(float* __restrict__ out)
{
    __shared__ __half SM[6144];
    float acc[4][4][4];
    const int row0 = blockIdx.x*128, col0 = blockIdx.y*128;
    gemm_tile_h1(g_ao, g_wo, row0, col0, SM, acc);
    const int tid = threadIdx.x, w = tid>>5, lane = tid&31;
    const int wm = w>>2, wn = w&3, g = lane>>2, tg = lane&3;
    #pragma unroll
    for (int mf = 0; mf < 4; mf++) {
        int r = row0 + wm*64 + mf*16 + g;
        #pragma unroll
        for (int nf = 0; nf < 4; nf++) {
            int c = col0 + wn*32 + nf*8 + tg*2;
            *(float2*)&out[(size_t)r*1024 + c] =
                make_float2(acc[mf][nf][0], acc[mf][nf][1]);
            *(float2*)&out[(size_t)(r+8)*1024 + c] =
                make_float2(acc[mf][nf][2], acc[mf][nf][3]);
        }
    }
}

// ---------------- launch ----------------
extern "C" void kernel_launch(void* const* d_in, const int* in_sizes, int n_in,
                              void* d_out, int out_size)
{
    (void)in_sizes; (void)n_in; (void)out_size;
    const float* q   = (const float*)d_in[0];
    const float* k   = (const float*)d_in[1];
    const float* v   = (const float*)d_in[2];
    const float* w_q = (const float*)d_in[3];
    const float* w_k = (const float*)d_in[4];
    const float* w_v = (const float*)d_in[5];
    const float* w_o = (const float*)d_in[6];
    float* out = (float*)d_out;

    dim3 tb(32, 8);
    prep_w <<<dim3(2, 32, 48), tb>>>(w_q, w_k, w_v);
    prep_wo<<<dim3(32, 32), tb>>>(w_o);

    proj<<<dim3(64, 8, 3), 256>>>(q, k, v);
    flash_attn<<<dim3(16, 64), 256>>>();
    out_gemm<<<dim3(64, 8), 256>>>(out);
}